// round 1
// baseline (speedup 1.0000x reference)
#include <cuda_runtime.h>
#include <cuda_bf16.h>

// Problem constants (fixed by the dataset)
constexpr int B   = 4096;
constexpr int T   = 200;
constexpr int F   = 36;
constexpr int H1  = 16;
constexpr int H2  = 32;
constexpr int H3  = 16;

// 8 threads cooperate on one batch element; 32 batches per 256-thread block.
constexpr int GRP = 8;
constexpr int BATCH_PER_BLOCK = 256 / GRP;   // 32
constexpr int GRID = B / BATCH_PER_BLOCK;    // 128

// Shared-memory layout (floats)
constexpr int OFF_W1X = 0;                    // 64 x 36
constexpr int OFF_W1H = OFF_W1X + 64 * 36;    // 64 x 16
constexpr int OFF_B1  = OFF_W1H + 64 * 16;    // 64
constexpr int OFF_W2X = OFF_B1  + 64;         // 128 x 16
constexpr int OFF_W2H = OFF_W2X + 128 * 16;   // 128 x 32
constexpr int OFF_B2  = OFF_W2H + 128 * 32;   // 128
constexpr int OFF_W3X = OFF_B2  + 128;        // 64 x 32
constexpr int OFF_W3H = OFF_W3X + 64 * 32;    // 64 x 16
constexpr int OFF_B3  = OFF_W3H + 64 * 16;    // 64
constexpr int SMEM_FLOATS = OFF_B3 + 64;      // 12800
constexpr int SMEM_BYTES  = SMEM_FLOATS * 4;  // 51200

// Collapsed head: out = h3 @ Wc^T + bc,  Wc: [6,16], bc: [6]
__device__ float g_Wc[6 * 16];
__device__ float g_bc[6];

__device__ __forceinline__ float sigf(float x) {
    return __fdividef(1.0f, 1.0f + __expf(-x));
}
__device__ __forceinline__ float tanh_(float x) {
    return __fdividef(2.0f, 1.0f + __expf(-2.0f * x)) - 1.0f;
}

// One LSTM step for one layer. H = hidden size, IN = input size.
// Each of the 8 group lanes owns U = H/8 hidden units.
// xin: replicated input vector (registers), h: replicated hidden state
// (registers, updated in place), c: this lane's owned cell states.
template <int H, int IN>
__device__ __forceinline__ void lstm_layer_step(
    const float* __restrict__ smWx, const float* __restrict__ smWh,
    const float* __restrict__ smB,
    const float (&xin)[IN], float (&h)[H], float (&c)[H / GRP], int k)
{
    constexpr int U = H / GRP;
    float a[4 * U];

    // bias init (bih+bhh precombined)
    #pragma unroll
    for (int q = 0; q < 4; q++)
        #pragma unroll
        for (int uu = 0; uu < U; uu++)
            a[q * U + uu] = smB[q * H + U * k + uu];

    // input projection: a += Wx[row] . xin
    #pragma unroll
    for (int j = 0; j < IN / 4; j++) {
        #pragma unroll
        for (int q = 0; q < 4; q++)
            #pragma unroll
            for (int uu = 0; uu < U; uu++) {
                const int r = q * H + U * k + uu;
                float4 w = *reinterpret_cast<const float4*>(smWx + r * IN + 4 * j);
                float acc = a[q * U + uu];
                acc = fmaf(w.x, xin[4 * j + 0], acc);
                acc = fmaf(w.y, xin[4 * j + 1], acc);
                acc = fmaf(w.z, xin[4 * j + 2], acc);
                acc = fmaf(w.w, xin[4 * j + 3], acc);
                a[q * U + uu] = acc;
            }
    }

    // recurrent projection: a += Wh[row] . h   (h = previous step's state)
    #pragma unroll
    for (int j = 0; j < H / 4; j++) {
        #pragma unroll
        for (int q = 0; q < 4; q++)
            #pragma unroll
            for (int uu = 0; uu < U; uu++) {
                const int r = q * H + U * k + uu;
                float4 w = *reinterpret_cast<const float4*>(smWh + r * H + 4 * j);
                float acc = a[q * U + uu];
                acc = fmaf(w.x, h[4 * j + 0], acc);
                acc = fmaf(w.y, h[4 * j + 1], acc);
                acc = fmaf(w.z, h[4 * j + 2], acc);
                acc = fmaf(w.w, h[4 * j + 3], acc);
                a[q * U + uu] = acc;
            }
    }

    // gate nonlinearities + cell update (PyTorch gate order i,f,g,o)
    float hn[U];
    #pragma unroll
    for (int uu = 0; uu < U; uu++) {
        float ig = sigf(a[0 * U + uu]);
        float fg = sigf(a[1 * U + uu]);
        float gg = tanh_(a[2 * U + uu]);
        float og = sigf(a[3 * U + uu]);
        float cc = fmaf(fg, c[uu], ig * gg);
        c[uu] = cc;
        hn[uu] = og * tanh_(cc);
    }

    // broadcast new h to all 8 lanes of the group
    #pragma unroll
    for (int s = 0; s < GRP; s++)
        #pragma unroll
        for (int uu = 0; uu < U; uu++)
            h[U * s + uu] = __shfl_sync(0xffffffffu, hn[uu], s, GRP);
}

__global__ void __launch_bounds__(256, 1) lstm_fused(
    const float* __restrict__ x,
    const float* __restrict__ Wih1, const float* __restrict__ Whh1,
    const float* __restrict__ bih1, const float* __restrict__ bhh1,
    const float* __restrict__ Wih2, const float* __restrict__ Whh2,
    const float* __restrict__ bih2, const float* __restrict__ bhh2,
    const float* __restrict__ Wih3, const float* __restrict__ Whh3,
    const float* __restrict__ bih3, const float* __restrict__ bhh3,
    float* __restrict__ out)
{
    extern __shared__ float sm[];
    const int tid = threadIdx.x;

    // cooperative weight staging
    for (int i = tid; i < 64 * 36; i += 256)  sm[OFF_W1X + i] = Wih1[i];
    for (int i = tid; i < 64 * 16; i += 256)  sm[OFF_W1H + i] = Whh1[i];
    for (int i = tid; i < 64; i += 256)       sm[OFF_B1 + i]  = bih1[i] + bhh1[i];
    for (int i = tid; i < 128 * 16; i += 256) sm[OFF_W2X + i] = Wih2[i];
    for (int i = tid; i < 128 * 32; i += 256) sm[OFF_W2H + i] = Whh2[i];
    for (int i = tid; i < 128; i += 256)      sm[OFF_B2 + i]  = bih2[i] + bhh2[i];
    for (int i = tid; i < 64 * 32; i += 256)  sm[OFF_W3X + i] = Wih3[i];
    for (int i = tid; i < 64 * 16; i += 256)  sm[OFF_W3H + i] = Whh3[i];
    for (int i = tid; i < 64; i += 256)       sm[OFF_B3 + i]  = bih3[i] + bhh3[i];
    __syncthreads();

    const int k = tid & (GRP - 1);       // lane within group
    const int g = tid >> 3;              // group within block
    const int b = blockIdx.x * BATCH_PER_BLOCK + g;

    float h1[H1], h2[H2], h3[H3];
    float c1[H1 / GRP], c2[H2 / GRP], c3[H3 / GRP];
    #pragma unroll
    for (int i = 0; i < H1; i++) h1[i] = 0.0f;
    #pragma unroll
    for (int i = 0; i < H2; i++) h2[i] = 0.0f;
    #pragma unroll
    for (int i = 0; i < H3; i++) h3[i] = 0.0f;
    #pragma unroll
    for (int i = 0; i < H1 / GRP; i++) c1[i] = 0.0f;
    #pragma unroll
    for (int i = 0; i < H2 / GRP; i++) c2[i] = 0.0f;
    #pragma unroll
    for (int i = 0; i < H3 / GRP; i++) c3[i] = 0.0f;

    const float4* xb = reinterpret_cast<const float4*>(x + (size_t)b * T * F);

    for (int t = 0; t < T; t++) {
        // load this step's input row (36 floats, 9 x float4, group-broadcast via L1)
        float xr[F];
        #pragma unroll
        for (int j = 0; j < F / 4; j++) {
            float4 v = __ldg(xb + (size_t)t * (F / 4) + j);
            xr[4 * j + 0] = v.x; xr[4 * j + 1] = v.y;
            xr[4 * j + 2] = v.z; xr[4 * j + 3] = v.w;
        }

        lstm_layer_step<H1, F>(sm + OFF_W1X, sm + OFF_W1H, sm + OFF_B1, xr, h1, c1, k);
        lstm_layer_step<H2, H1>(sm + OFF_W2X, sm + OFF_W2H, sm + OFF_B2, h1, h2, c2, k);
        lstm_layer_step<H3, H2>(sm + OFF_W3X, sm + OFF_W3H, sm + OFF_B3, h2, h3, c3, k);
    }

    // collapsed linear head: lanes 0..5 each produce one output logit
    if (k < 6) {
        float acc = g_bc[k];
        #pragma unroll
        for (int u = 0; u < H3; u++)
            acc = fmaf(h3[u], g_Wc[k * H3 + u], acc);
        out[(size_t)b * 6 + k] = acc;
    }
}

// Collapse the 3 bias-only-linear head layers into Wc [6,16], bc [6].
__global__ void head_precompute(
    const float* __restrict__ Wfc1, const float* __restrict__ bfc1,
    const float* __restrict__ Wfc2, const float* __restrict__ bfc2,
    const float* __restrict__ Wcls, const float* __restrict__ bcls)
{
    __shared__ float tmp[6 * 128];   // W_cls @ W_fc2  -> [6,128]
    const int tid = threadIdx.x;

    for (int idx = tid; idx < 6 * 128; idx += blockDim.x) {
        int j = idx / 128, p = idx % 128;
        float s = 0.0f;
        for (int q = 0; q < 32; q++)
            s += Wcls[j * 32 + q] * Wfc2[q * 128 + p];
        tmp[idx] = s;
    }
    __syncthreads();

    for (int idx = tid; idx < 6 * 16; idx += blockDim.x) {
        int j = idx / 16, u = idx % 16;
        float s = 0.0f;
        for (int p = 0; p < 128; p++)
            s += tmp[j * 128 + p] * Wfc1[p * 16 + u];
        g_Wc[idx] = s;
    }
    if (tid < 6) {
        float s = bcls[tid];
        for (int q = 0; q < 32; q++)
            s += Wcls[tid * 32 + q] * bfc2[q];
        for (int p = 0; p < 128; p++)
            s += tmp[tid * 128 + p] * bfc1[p];
        g_bc[tid] = s;
    }
}

extern "C" void kernel_launch(void* const* d_in, const int* in_sizes, int n_in,
                              void* d_out, int out_size)
{
    (void)in_sizes; (void)n_in; (void)out_size;
    const float* x    = (const float*)d_in[0];
    const float* Wih1 = (const float*)d_in[1];
    const float* Whh1 = (const float*)d_in[2];
    const float* bih1 = (const float*)d_in[3];
    const float* bhh1 = (const float*)d_in[4];
    const float* Wih2 = (const float*)d_in[5];
    const float* Whh2 = (const float*)d_in[6];
    const float* bih2 = (const float*)d_in[7];
    const float* bhh2 = (const float*)d_in[8];
    const float* Wih3 = (const float*)d_in[9];
    const float* Whh3 = (const float*)d_in[10];
    const float* bih3 = (const float*)d_in[11];
    const float* bhh3 = (const float*)d_in[12];
    const float* Wfc1 = (const float*)d_in[13];
    const float* bfc1 = (const float*)d_in[14];
    const float* Wfc2 = (const float*)d_in[15];
    const float* bfc2 = (const float*)d_in[16];
    const float* Wcls = (const float*)d_in[17];
    const float* bcls = (const float*)d_in[18];
    float* out = (float*)d_out;

    static bool attr_set = false;
    if (!attr_set) {
        cudaFuncSetAttribute(lstm_fused,
                             cudaFuncAttributeMaxDynamicSharedMemorySize,
                             SMEM_BYTES);
        attr_set = true;
    }

    head_precompute<<<1, 256>>>(Wfc1, bfc1, Wfc2, bfc2, Wcls, bcls);
    lstm_fused<<<GRID, 256, SMEM_BYTES>>>(
        x, Wih1, Whh1, bih1, bhh1, Wih2, Whh2, bih2, bhh2,
        Wih3, Whh3, bih3, bhh3, out);
}

// round 2
// speedup vs baseline: 4.4029x; 4.4029x over previous
#include <cuda_runtime.h>
#include <cuda_bf16.h>

typedef unsigned long long u64;

// Problem constants
constexpr int B  = 4096;
constexpr int T  = 200;
constexpr int F  = 36;
constexpr int H1 = 16;
constexpr int H2 = 32;
constexpr int H3 = 16;

constexpr int GRP     = 8;              // lanes cooperating on one batch element
constexpr int THREADS = 256;
constexpr int BPB     = THREADS / GRP;  // 32 batches per block
constexpr int GRID    = B / BPB;        // 128 blocks

// ---------------------------------------------------------------------------
// Per-layer skewed, unit-pair-interleaved shared-memory layout.
// Lane k owns rows { q*H + U*k + uu : q in 0..3, uu in 0..U-1 }.
// Rows are grouped into pairs p = q*(U/2) + (uu>>1); each pair is stored
// element-interleaved: [A_j, B_j, A_{j+1}, B_{j+1}, ...] so one LDS.128 feeds
// two FFMA2 (packed f32x2). Lane blocks are skewed by +4 floats so lane k's
// addresses sit at +16k bytes (mod 128) -> conflict-free across all 8 lanes.
// ---------------------------------------------------------------------------
template<int H, int IN> struct LL {
    static constexpr int U = H / GRP;               // units per lane
    static constexpr int P = 2 * U;                 // row-pairs per lane
    static constexpr int whOff = P * 2 * IN;        // Wh section offset (floats)
    static constexpr int laneStride = P * 2 * (IN + H) + 4;  // +4 skew
    static constexpr int blockFloats = GRP * laneStride;
};
using LY1 = LL<H1, F>;
using LY2 = LL<H2, H1>;
using LY3 = LL<H3, H2>;

constexpr int OFF_L1 = 0;
constexpr int OFF_L2 = OFF_L1 + LY1::blockFloats;
constexpr int OFF_L3 = OFF_L2 + LY2::blockFloats;
constexpr int OFF_B1 = OFF_L3 + LY3::blockFloats;   // biases, pair-interleaved
constexpr int OFF_B2 = OFF_B1 + 4 * H1;
constexpr int OFF_B3 = OFF_B2 + 4 * H2;
constexpr int SMEM_FLOATS = OFF_B3 + 4 * H3;
constexpr int SMEM_BYTES  = SMEM_FLOATS * 4;        // ~51.6 KB

// Collapsed head: out = h3 @ Wc^T + bc
__device__ float g_Wc[6 * 16];
__device__ float g_bc[6];

// ---- packed f32x2 helpers (sm_100+) ----
__device__ __forceinline__ void fma2(u64 &acc, u64 w, u64 x) {
    asm("fma.rn.f32x2 %0, %1, %2, %0;" : "+l"(acc) : "l"(w), "l"(x));
}
__device__ __forceinline__ u64 pk(float v) {
    u64 r; asm("mov.b64 %0, {%1, %1};" : "=l"(r) : "f"(v)); return r;
}
__device__ __forceinline__ void upk(u64 v, float &lo, float &hi) {
    asm("mov.b64 {%0, %1}, %2;" : "=f"(lo), "=f"(hi) : "l"(v));
}

__device__ __forceinline__ float sigf(float x) {
    return __fdividef(1.0f, 1.0f + __expf(-x));
}
__device__ __forceinline__ float tanh_(float x) {
    return __fdividef(2.0f, 1.0f + __expf(-2.0f * x)) - 1.0f;
}

// ---- staging: repack global weights into the skewed interleaved layout ----
template<int H, int IN>
__device__ void stage(float* base, float* biasBase,
                      const float* __restrict__ Wx, const float* __restrict__ Wh,
                      const float* __restrict__ bih, const float* __restrict__ bhh,
                      int tid)
{
    using L = LL<H, IN>;
    for (int idx = tid; idx < 4 * H * IN; idx += THREADS) {
        int r = idx / IN, j = idx - r * IN;
        int q = r / H,    m = r - q * H;
        int k = m / L::U, uu = m - k * L::U;
        int p = q * (L::U / 2) + (uu >> 1), slot = uu & 1;
        base[k * L::laneStride + p * 2 * IN + 2 * j + slot] = Wx[idx];
    }
    for (int idx = tid; idx < 4 * H * H; idx += THREADS) {
        int r = idx / H,  j = idx - r * H;
        int q = r / H,    m = r - q * H;
        int k = m / L::U, uu = m - k * L::U;
        int p = q * (L::U / 2) + (uu >> 1), slot = uu & 1;
        base[k * L::laneStride + L::whOff + p * 2 * H + 2 * j + slot] = Wh[idx];
    }
    for (int r = tid; r < 4 * H; r += THREADS) {
        int q = r / H,    m = r - q * H;
        int k = m / L::U, uu = m - k * L::U;
        int p = q * (L::U / 2) + (uu >> 1), slot = uu & 1;
        biasBase[(k * L::P + p) * 2 + slot] = bih[r] + bhh[r];
    }
}

// ---- one LSTM layer step ----
template<int H, int IN>
__device__ __forceinline__ void lstm_step(
    const float* __restrict__ laneW, const u64* __restrict__ laneB,
    const float (&xin)[IN], float (&h)[H], float (&c)[H / GRP])
{
    using L = LL<H, IN>;
    constexpr int U = L::U, P = L::P;

    u64 acc[P];
    #pragma unroll
    for (int p = 0; p < P; p++) acc[p] = laneB[p];

    // input projection
    #pragma unroll
    for (int j = 0; j < IN; j += 2) {
        u64 x0 = pk(xin[j]), x1 = pk(xin[j + 1]);
        #pragma unroll
        for (int p = 0; p < P; p++) {
            ulonglong2 w = *reinterpret_cast<const ulonglong2*>(laneW + p * 2 * IN + 2 * j);
            fma2(acc[p], w.x, x0);
            fma2(acc[p], w.y, x1);
        }
    }
    // recurrent projection (uses previous-step h)
    #pragma unroll
    for (int j = 0; j < H; j += 2) {
        u64 x0 = pk(h[j]), x1 = pk(h[j + 1]);
        #pragma unroll
        for (int p = 0; p < P; p++) {
            ulonglong2 w = *reinterpret_cast<const ulonglong2*>(laneW + L::whOff + p * 2 * H + 2 * j);
            fma2(acc[p], w.x, x0);
            fma2(acc[p], w.y, x1);
        }
    }

    // unpack gate pre-activations: pair p=(q,up) holds units (2up, 2up+1) of gate q
    float ga[4 * U];
    #pragma unroll
    for (int q = 0; q < 4; q++)
        #pragma unroll
        for (int up = 0; up < U / 2; up++)
            upk(acc[q * (U / 2) + up], ga[q * U + 2 * up], ga[q * U + 2 * up + 1]);

    float hn[U];
    #pragma unroll
    for (int uu = 0; uu < U; uu++) {
        float ig = sigf(ga[0 * U + uu]);
        float fg = sigf(ga[1 * U + uu]);
        float gg = tanh_(ga[2 * U + uu]);
        float og = sigf(ga[3 * U + uu]);
        float cc = fmaf(fg, c[uu], ig * gg);
        c[uu] = cc;
        hn[uu] = og * tanh_(cc);
    }
    // broadcast new h to all 8 lanes of the group
    #pragma unroll
    for (int s = 0; s < GRP; s++)
        #pragma unroll
        for (int uu = 0; uu < U; uu++)
            h[U * s + uu] = __shfl_sync(0xffffffffu, hn[uu], s, GRP);
}

__global__ void __launch_bounds__(THREADS, 1) lstm_fused(
    const float* __restrict__ x,
    const float* __restrict__ Wih1, const float* __restrict__ Whh1,
    const float* __restrict__ bih1, const float* __restrict__ bhh1,
    const float* __restrict__ Wih2, const float* __restrict__ Whh2,
    const float* __restrict__ bih2, const float* __restrict__ bhh2,
    const float* __restrict__ Wih3, const float* __restrict__ Whh3,
    const float* __restrict__ bih3, const float* __restrict__ bhh3,
    float* __restrict__ out)
{
    extern __shared__ float sm[];
    const int tid = threadIdx.x;

    stage<H1, F >(sm + OFF_L1, sm + OFF_B1, Wih1, Whh1, bih1, bhh1, tid);
    stage<H2, H1>(sm + OFF_L2, sm + OFF_B2, Wih2, Whh2, bih2, bhh2, tid);
    stage<H3, H2>(sm + OFF_L3, sm + OFF_B3, Wih3, Whh3, bih3, bhh3, tid);
    __syncthreads();

    const int k = tid & (GRP - 1);
    const int g = tid >> 3;
    const int b = blockIdx.x * BPB + g;

    const float* laneW1 = sm + OFF_L1 + k * LY1::laneStride;
    const float* laneW2 = sm + OFF_L2 + k * LY2::laneStride;
    const float* laneW3 = sm + OFF_L3 + k * LY3::laneStride;
    const u64* laneB1 = reinterpret_cast<const u64*>(sm + OFF_B1) + k * LY1::P;
    const u64* laneB2 = reinterpret_cast<const u64*>(sm + OFF_B2) + k * LY2::P;
    const u64* laneB3 = reinterpret_cast<const u64*>(sm + OFF_B3) + k * LY3::P;

    float h1[H1], h2[H2], h3[H3];
    float c1[H1 / GRP], c2[H2 / GRP], c3[H3 / GRP];
    #pragma unroll
    for (int i = 0; i < H1; i++) h1[i] = 0.0f;
    #pragma unroll
    for (int i = 0; i < H2; i++) h2[i] = 0.0f;
    #pragma unroll
    for (int i = 0; i < H3; i++) h3[i] = 0.0f;
    #pragma unroll
    for (int i = 0; i < H1 / GRP; i++) c1[i] = 0.0f;
    #pragma unroll
    for (int i = 0; i < H2 / GRP; i++) c2[i] = 0.0f;
    #pragma unroll
    for (int i = 0; i < H3 / GRP; i++) c3[i] = 0.0f;

    const float4* xb = reinterpret_cast<const float4*>(x + (size_t)b * T * F);

    for (int t = 0; t < T; t++) {
        float xr[F];
        #pragma unroll
        for (int j = 0; j < F / 4; j++) {
            float4 v = __ldg(xb + (size_t)t * (F / 4) + j);
            xr[4 * j + 0] = v.x; xr[4 * j + 1] = v.y;
            xr[4 * j + 2] = v.z; xr[4 * j + 3] = v.w;
        }
        lstm_step<H1, F >(laneW1, laneB1, xr, h1, c1);
        lstm_step<H2, H1>(laneW2, laneB2, h1, h2, c2);
        lstm_step<H3, H2>(laneW3, laneB3, h2, h3, c3);
    }

    if (k < 6) {
        float acc = g_bc[k];
        #pragma unroll
        for (int u = 0; u < H3; u++)
            acc = fmaf(h3[u], g_Wc[k * H3 + u], acc);
        out[(size_t)b * 6 + k] = acc;
    }
}

// Collapse the 3 linear head layers (no nonlinearity) into Wc [6,16], bc [6].
__global__ void head_precompute(
    const float* __restrict__ Wfc1, const float* __restrict__ bfc1,
    const float* __restrict__ Wfc2, const float* __restrict__ bfc2,
    const float* __restrict__ Wcls, const float* __restrict__ bcls)
{
    __shared__ float tmp[6 * 128];   // W_cls @ W_fc2 -> [6,128]
    const int tid = threadIdx.x;

    for (int idx = tid; idx < 6 * 128; idx += blockDim.x) {
        int j = idx / 128, p = idx % 128;
        float s = 0.0f;
        for (int q = 0; q < 32; q++)
            s += Wcls[j * 32 + q] * Wfc2[q * 128 + p];
        tmp[idx] = s;
    }
    __syncthreads();

    for (int idx = tid; idx < 6 * 16; idx += blockDim.x) {
        int j = idx / 16, u = idx % 16;
        float s = 0.0f;
        for (int p = 0; p < 128; p++)
            s += tmp[j * 128 + p] * Wfc1[p * 16 + u];
        g_Wc[idx] = s;
    }
    if (tid < 6) {
        float s = bcls[tid];
        for (int q = 0; q < 32; q++)
            s += Wcls[tid * 32 + q] * bfc2[q];
        for (int p = 0; p < 128; p++)
            s += tmp[tid * 128 + p] * bfc1[p];
        g_bc[tid] = s;
    }
}

extern "C" void kernel_launch(void* const* d_in, const int* in_sizes, int n_in,
                              void* d_out, int out_size)
{
    (void)in_sizes; (void)n_in; (void)out_size;
    const float* x    = (const float*)d_in[0];
    const float* Wih1 = (const float*)d_in[1];
    const float* Whh1 = (const float*)d_in[2];
    const float* bih1 = (const float*)d_in[3];
    const float* bhh1 = (const float*)d_in[4];
    const float* Wih2 = (const float*)d_in[5];
    const float* Whh2 = (const float*)d_in[6];
    const float* bih2 = (const float*)d_in[7];
    const float* bhh2 = (const float*)d_in[8];
    const float* Wih3 = (const float*)d_in[9];
    const float* Whh3 = (const float*)d_in[10];
    const float* bih3 = (const float*)d_in[11];
    const float* bhh3 = (const float*)d_in[12];
    const float* Wfc1 = (const float*)d_in[13];
    const float* bfc1 = (const float*)d_in[14];
    const float* Wfc2 = (const float*)d_in[15];
    const float* bfc2 = (const float*)d_in[16];
    const float* Wcls = (const float*)d_in[17];
    const float* bcls = (const float*)d_in[18];
    float* out = (float*)d_out;

    static bool attr_set = false;
    if (!attr_set) {
        cudaFuncSetAttribute(lstm_fused,
                             cudaFuncAttributeMaxDynamicSharedMemorySize,
                             SMEM_BYTES);
        attr_set = true;
    }

    head_precompute<<<1, 256>>>(Wfc1, bfc1, Wfc2, bfc2, Wcls, bcls);
    lstm_fused<<<GRID, THREADS, SMEM_BYTES>>>(
        x, Wih1, Whh1, bih1, bhh1, Wih2, Whh2, bih2, bhh2,
        Wih3, Whh3, bih3, bhh3, out);
}

// round 3
// speedup vs baseline: 8.1299x; 1.8465x over previous
#include <cuda_runtime.h>
#include <cuda_bf16.h>

typedef unsigned long long u64;

// Problem constants
constexpr int B  = 4096;
constexpr int T  = 200;
constexpr int F  = 36;
constexpr int H1 = 16;
constexpr int H2 = 32;
constexpr int H3 = 16;

constexpr int GRP     = 8;               // lanes cooperating on one batch pair
constexpr int NB      = 2;               // batches per thread (weight reuse)
constexpr int THREADS = 128;             // 4 warps -> one per SMSP
constexpr int GROUPS  = THREADS / GRP;   // 16 groups per block
constexpr int BPB     = GROUPS * NB;     // 32 batches per block
constexpr int GRID    = B / BPB;         // 128 blocks

// ---------------------------------------------------------------------------
// Skewed, unit-pair-interleaved weight layout (unchanged from R2):
// lane k's block starts at k*laneStride; laneStride ≡ 4 (mod 32) floats so the
// 8 lanes hit 8 distinct 16B bank groups on every LDS.128.
// ---------------------------------------------------------------------------
template<int H, int IN> struct LL {
    static constexpr int U = H / GRP;
    static constexpr int P = 2 * U;                       // row-pairs per lane
    static constexpr int whOff = P * 2 * IN;
    static constexpr int laneStride = P * 2 * (IN + H) + 4;
    static constexpr int blockFloats = GRP * laneStride;
};
using LY1 = LL<H1, F>;
using LY2 = LL<H2, H1>;
using LY3 = LL<H3, H2>;

constexpr int OFF_L1 = 0;
constexpr int OFF_L2 = OFF_L1 + LY1::blockFloats;
constexpr int OFF_L3 = OFF_L2 + LY2::blockFloats;
constexpr int OFF_B1 = OFF_L3 + LY3::blockFloats;
constexpr int OFF_B2 = OFF_B1 + 4 * H1;
constexpr int OFF_B3 = OFF_B2 + 4 * H2;
constexpr int SMEM_FLOATS = OFF_B3 + 4 * H3;
constexpr int SMEM_BYTES  = SMEM_FLOATS * 4;   // ~51.6 KB

__device__ float g_Wc[6 * 16];
__device__ float g_bc[6];

// ---- packed f32x2 helpers ----
__device__ __forceinline__ void fma2(u64 &acc, u64 w, u64 x) {
    asm("fma.rn.f32x2 %0, %1, %2, %0;" : "+l"(acc) : "l"(w), "l"(x));
}
__device__ __forceinline__ u64 pk(float v) {
    u64 r; asm("mov.b64 %0, {%1, %1};" : "=l"(r) : "f"(v)); return r;
}
__device__ __forceinline__ void upk(u64 v, float &lo, float &hi) {
    asm("mov.b64 {%0, %1}, %2;" : "=f"(lo), "=f"(hi) : "l"(v));
}
__device__ __forceinline__ float sigf(float x) {
    return __fdividef(1.0f, 1.0f + __expf(-x));
}
__device__ __forceinline__ float tanh_(float x) {
    return __fdividef(2.0f, 1.0f + __expf(-2.0f * x)) - 1.0f;
}

// ---- x accessors: gmem stream (layer 1) or register h (layers 2/3) ----
struct XG {
    const float* a; const float* b;
    __device__ __forceinline__ float2 operator()(int j) const {
        return make_float2(__ldg(a + j), __ldg(b + j));
    }
};
template<int N> struct XR {
    const float (&a)[N]; const float (&b)[N];
    __device__ __forceinline__ float2 operator()(int j) const {
        return make_float2(a[j], b[j]);
    }
};

// ---- one LSTM layer step for two batch elements sharing weight loads ----
template<int H, int IN, typename GX>
__device__ __forceinline__ void lstm_core(
    const float* __restrict__ laneW, const u64* __restrict__ laneB,
    GX gx, float (&ha)[H], float (&hb)[H],
    float (&ca)[H / GRP], float (&cb)[H / GRP])
{
    using L = LL<H, IN>;
    constexpr int U = L::U, P = L::P;

    u64 Aa[P], Ab[P];
    #pragma unroll
    for (int p = 0; p < P; p++) { u64 bv = laneB[p]; Aa[p] = bv; Ab[p] = bv; }

    // input projection — one 16B weight load feeds 4 FFMA2
    #pragma unroll
    for (int j = 0; j < IN; j += 2) {
        float2 x0 = gx(j), x1 = gx(j + 1);
        u64 xa0 = pk(x0.x), xb0 = pk(x0.y);
        u64 xa1 = pk(x1.x), xb1 = pk(x1.y);
        #pragma unroll
        for (int p = 0; p < P; p++) {
            ulonglong2 w = *reinterpret_cast<const ulonglong2*>(laneW + p * 2 * IN + 2 * j);
            fma2(Aa[p], w.x, xa0);
            fma2(Ab[p], w.x, xb0);
            fma2(Aa[p], w.y, xa1);
            fma2(Ab[p], w.y, xb1);
        }
    }
    // recurrent projection
    #pragma unroll
    for (int j = 0; j < H; j += 2) {
        u64 xa0 = pk(ha[j]),     xb0 = pk(hb[j]);
        u64 xa1 = pk(ha[j + 1]), xb1 = pk(hb[j + 1]);
        #pragma unroll
        for (int p = 0; p < P; p++) {
            ulonglong2 w = *reinterpret_cast<const ulonglong2*>(laneW + L::whOff + p * 2 * H + 2 * j);
            fma2(Aa[p], w.x, xa0);
            fma2(Ab[p], w.x, xb0);
            fma2(Aa[p], w.y, xa1);
            fma2(Ab[p], w.y, xb1);
        }
    }

    // gates for both batches
    float ga[4 * U], gb[4 * U];
    #pragma unroll
    for (int q = 0; q < 4; q++)
        #pragma unroll
        for (int up = 0; up < U / 2; up++) {
            upk(Aa[q * (U / 2) + up], ga[q * U + 2 * up], ga[q * U + 2 * up + 1]);
            upk(Ab[q * (U / 2) + up], gb[q * U + 2 * up], gb[q * U + 2 * up + 1]);
        }

    float hna[U], hnb[U];
    #pragma unroll
    for (int uu = 0; uu < U; uu++) {
        float iga = sigf(ga[0 * U + uu]);
        float fga = sigf(ga[1 * U + uu]);
        float gga = tanh_(ga[2 * U + uu]);
        float oga = sigf(ga[3 * U + uu]);
        float cca = fmaf(fga, ca[uu], iga * gga);
        ca[uu] = cca;
        hna[uu] = oga * tanh_(cca);

        float igb = sigf(gb[0 * U + uu]);
        float fgb = sigf(gb[1 * U + uu]);
        float ggb = tanh_(gb[2 * U + uu]);
        float ogb = sigf(gb[3 * U + uu]);
        float ccb = fmaf(fgb, cb[uu], igb * ggb);
        cb[uu] = ccb;
        hnb[uu] = ogb * tanh_(ccb);
    }

    // broadcast new h across the 8-lane group, both batches
    #pragma unroll
    for (int s = 0; s < GRP; s++)
        #pragma unroll
        for (int uu = 0; uu < U; uu++) {
            ha[U * s + uu] = __shfl_sync(0xffffffffu, hna[uu], s, GRP);
            hb[U * s + uu] = __shfl_sync(0xffffffffu, hnb[uu], s, GRP);
        }
}

// ---- staging: repack global weights into skewed interleaved layout ----
template<int H, int IN>
__device__ void stage(float* base, float* biasBase,
                      const float* __restrict__ Wx, const float* __restrict__ Wh,
                      const float* __restrict__ bih, const float* __restrict__ bhh,
                      int tid)
{
    using L = LL<H, IN>;
    for (int idx = tid; idx < 4 * H * IN; idx += THREADS) {
        int r = idx / IN, j = idx - r * IN;
        int q = r / H,    m = r - q * H;
        int k = m / L::U, uu = m - k * L::U;
        int p = q * (L::U / 2) + (uu >> 1), slot = uu & 1;
        base[k * L::laneStride + p * 2 * IN + 2 * j + slot] = Wx[idx];
    }
    for (int idx = tid; idx < 4 * H * H; idx += THREADS) {
        int r = idx / H,  j = idx - r * H;
        int q = r / H,    m = r - q * H;
        int k = m / L::U, uu = m - k * L::U;
        int p = q * (L::U / 2) + (uu >> 1), slot = uu & 1;
        base[k * L::laneStride + L::whOff + p * 2 * H + 2 * j + slot] = Wh[idx];
    }
    for (int r = tid; r < 4 * H; r += THREADS) {
        int q = r / H,    m = r - q * H;
        int k = m / L::U, uu = m - k * L::U;
        int p = q * (L::U / 2) + (uu >> 1), slot = uu & 1;
        biasBase[(k * L::P + p) * 2 + slot] = bih[r] + bhh[r];
    }
}

__global__ void __launch_bounds__(THREADS, 1) lstm_fused(
    const float* __restrict__ x,
    const float* __restrict__ Wih1, const float* __restrict__ Whh1,
    const float* __restrict__ bih1, const float* __restrict__ bhh1,
    const float* __restrict__ Wih2, const float* __restrict__ Whh2,
    const float* __restrict__ bih2, const float* __restrict__ bhh2,
    const float* __restrict__ Wih3, const float* __restrict__ Whh3,
    const float* __restrict__ bih3, const float* __restrict__ bhh3,
    float* __restrict__ out)
{
    extern __shared__ float sm[];
    const int tid = threadIdx.x;

    stage<H1, F >(sm + OFF_L1, sm + OFF_B1, Wih1, Whh1, bih1, bhh1, tid);
    stage<H2, H1>(sm + OFF_L2, sm + OFF_B2, Wih2, Whh2, bih2, bhh2, tid);
    stage<H3, H2>(sm + OFF_L3, sm + OFF_B3, Wih3, Whh3, bih3, bhh3, tid);
    __syncthreads();

    const int k  = tid & (GRP - 1);
    const int g  = tid >> 3;                      // group 0..15
    const int b0 = blockIdx.x * BPB + g * NB;     // this group's two batches
    const int b1 = b0 + 1;

    const float* laneW1 = sm + OFF_L1 + k * LY1::laneStride;
    const float* laneW2 = sm + OFF_L2 + k * LY2::laneStride;
    const float* laneW3 = sm + OFF_L3 + k * LY3::laneStride;
    const u64* laneB1 = reinterpret_cast<const u64*>(sm + OFF_B1) + k * LY1::P;
    const u64* laneB2 = reinterpret_cast<const u64*>(sm + OFF_B2) + k * LY2::P;
    const u64* laneB3 = reinterpret_cast<const u64*>(sm + OFF_B3) + k * LY3::P;

    float h1a[H1], h1b[H1], h2a[H2], h2b[H2], h3a[H3], h3b[H3];
    float c1a[H1 / GRP], c1b[H1 / GRP];
    float c2a[H2 / GRP], c2b[H2 / GRP];
    float c3a[H3 / GRP], c3b[H3 / GRP];
    #pragma unroll
    for (int i = 0; i < H1; i++) { h1a[i] = 0.0f; h1b[i] = 0.0f; }
    #pragma unroll
    for (int i = 0; i < H2; i++) { h2a[i] = 0.0f; h2b[i] = 0.0f; }
    #pragma unroll
    for (int i = 0; i < H3; i++) { h3a[i] = 0.0f; h3b[i] = 0.0f; }
    #pragma unroll
    for (int i = 0; i < H1 / GRP; i++) { c1a[i] = 0.0f; c1b[i] = 0.0f; }
    #pragma unroll
    for (int i = 0; i < H2 / GRP; i++) { c2a[i] = 0.0f; c2b[i] = 0.0f; }
    #pragma unroll
    for (int i = 0; i < H3 / GRP; i++) { c3a[i] = 0.0f; c3b[i] = 0.0f; }

    const float* xa = x + (size_t)b0 * T * F;
    const float* xb = x + (size_t)b1 * T * F;

    for (int t = 0; t < T; t++) {
        XG gx1{xa + t * F, xb + t * F};
        lstm_core<H1, F >(laneW1, laneB1, gx1,            h1a, h1b, c1a, c1b);
        lstm_core<H2, H1>(laneW2, laneB2, XR<H1>{h1a, h1b}, h2a, h2b, c2a, c2b);
        lstm_core<H3, H2>(laneW3, laneB3, XR<H2>{h2a, h2b}, h3a, h3b, c3a, c3b);
    }

    if (k < 6) {
        float acc0 = g_bc[k], acc1 = g_bc[k];
        #pragma unroll
        for (int u = 0; u < H3; u++) {
            float wv = g_Wc[k * H3 + u];
            acc0 = fmaf(h3a[u], wv, acc0);
            acc1 = fmaf(h3b[u], wv, acc1);
        }
        out[(size_t)b0 * 6 + k] = acc0;
        out[(size_t)b1 * 6 + k] = acc1;
    }
}

// Collapse the 3 linear head layers into Wc [6,16], bc [6].
__global__ void head_precompute(
    const float* __restrict__ Wfc1, const float* __restrict__ bfc1,
    const float* __restrict__ Wfc2, const float* __restrict__ bfc2,
    const float* __restrict__ Wcls, const float* __restrict__ bcls)
{
    __shared__ float tmp[6 * 128];
    const int tid = threadIdx.x;

    for (int idx = tid; idx < 6 * 128; idx += blockDim.x) {
        int j = idx / 128, p = idx % 128;
        float s = 0.0f;
        for (int q = 0; q < 32; q++)
            s += Wcls[j * 32 + q] * Wfc2[q * 128 + p];
        tmp[idx] = s;
    }
    __syncthreads();

    for (int idx = tid; idx < 6 * 16; idx += blockDim.x) {
        int j = idx / 16, u = idx % 16;
        float s = 0.0f;
        for (int p = 0; p < 128; p++)
            s += tmp[j * 128 + p] * Wfc1[p * 16 + u];
        g_Wc[idx] = s;
    }
    if (tid < 6) {
        float s = bcls[tid];
        for (int q = 0; q < 32; q++)
            s += Wcls[tid * 32 + q] * bfc2[q];
        for (int p = 0; p < 128; p++)
            s += tmp[tid * 128 + p] * bfc1[p];
        g_bc[tid] = s;
    }
}

extern "C" void kernel_launch(void* const* d_in, const int* in_sizes, int n_in,
                              void* d_out, int out_size)
{
    (void)in_sizes; (void)n_in; (void)out_size;
    const float* x    = (const float*)d_in[0];
    const float* Wih1 = (const float*)d_in[1];
    const float* Whh1 = (const float*)d_in[2];
    const float* bih1 = (const float*)d_in[3];
    const float* bhh1 = (const float*)d_in[4];
    const float* Wih2 = (const float*)d_in[5];
    const float* Whh2 = (const float*)d_in[6];
    const float* bih2 = (const float*)d_in[7];
    const float* bhh2 = (const float*)d_in[8];
    const float* Wih3 = (const float*)d_in[9];
    const float* Whh3 = (const float*)d_in[10];
    const float* bih3 = (const float*)d_in[11];
    const float* bhh3 = (const float*)d_in[12];
    const float* Wfc1 = (const float*)d_in[13];
    const float* bfc1 = (const float*)d_in[14];
    const float* Wfc2 = (const float*)d_in[15];
    const float* bfc2 = (const float*)d_in[16];
    const float* Wcls = (const float*)d_in[17];
    const float* bcls = (const float*)d_in[18];
    float* out = (float*)d_out;

    static bool attr_set = false;
    if (!attr_set) {
        cudaFuncSetAttribute(lstm_fused,
                             cudaFuncAttributeMaxDynamicSharedMemorySize,
                             SMEM_BYTES);
        attr_set = true;
    }

    head_precompute<<<1, 256>>>(Wfc1, bfc1, Wfc2, bfc2, Wcls, bcls);
    lstm_fused<<<GRID, THREADS, SMEM_BYTES>>>(
        x, Wih1, Whh1, bih1, bhh1, Wih2, Whh2, bih2, bhh2,
        Wih3, Whh3, bih3, bhh3, out);
}